// round 1
// baseline (speedup 1.0000x reference)
#include <cuda_runtime.h>
#include <cuda_bf16.h>
#include <math.h>

// ---------------- problem constants ----------------
#define BATCH 8
#define TSTEPS 16
#define CIN0 192
#define HC0 64
#define HC1 32
#define HC2 64
#define IMG_H 28
#define IMG_W 28
#define HW 784

// ---------------- device scratch (no allocs allowed) ----------------
// gx0 precompute: (B*T, 4*HC0, 784)
__device__ float g_gx0[(size_t)BATCH * TSTEPS * 4 * HC0 * HW];
// gates scratch: max (B, 4*64, 784)
__device__ float g_gates[(size_t)BATCH * 4 * 64 * HW];
// state buffers packed: h0,c0,h1,c1,h2,c2
#define OFF_H0 0
#define OFF_C0 (OFF_H0 + BATCH * HC0 * HW)
#define OFF_H1 (OFF_C0 + BATCH * HC0 * HW)
#define OFF_C1 (OFF_H1 + BATCH * HC1 * HW)
#define OFF_H2 (OFF_C1 + BATCH * HC1 * HW)
#define OFF_C2 (OFF_H2 + BATCH * HC2 * HW)
#define NSTATE (OFF_C2 + BATCH * HC2 * HW)
__device__ float g_state[NSTATE];

// ---------------- init ----------------
__global__ void init_zero_kernel(float* p, int n) {
    int i = blockIdx.x * blockDim.x + threadIdx.x;
    if (i < n) p[i] = 0.f;
}

// ---------------- conv 3x3 SAME, dual-input, fp32 direct ----------------
// out(n, oc, 28,28) = sum over inA (cinA ch, weights WA) + inB (cinB ch, WB)
//                     + bias[oc] + pre[n*preStride + oc*784 + px]
// Block: one n, 8 output channels, full 28x28 spatial.
// 224 threads (7 warps); threads 0..195 compute (7 row-groups x 28 cols, 4 rows each).
__global__ void __launch_bounds__(224) conv3x3_kernel(
    const float* __restrict__ inA, int cinA, const float* __restrict__ WA,
    const float* __restrict__ inB, int cinB, const float* __restrict__ WB,
    const float* __restrict__ bias,
    const float* __restrict__ pre, size_t preStride,
    float* __restrict__ out, int OC)
{
    __shared__ __align__(16) float s_in[30 * 30];
    __shared__ __align__(16) float s_w[8 * 12];

    const int n   = blockIdx.x;
    const int ocg = blockIdx.y;      // base oc = ocg*8
    const int tid = threadIdx.x;
    const bool active = (tid < 196);
    const int tr = tid / 28;         // 0..6 (valid when active)
    const int tc = tid % 28;
    const int r0 = tr * 4;

    float acc[8][4];
#pragma unroll
    for (int oc = 0; oc < 8; ++oc)
#pragma unroll
        for (int p = 0; p < 4; ++p) acc[oc][p] = 0.f;

    const int cinT = cinA + cinB;
    for (int ci = 0; ci < cinT; ++ci) {
        const float* src;
        const float* wsrc;
        int wstride;
        if (ci < cinA) {
            src = inA + ((size_t)n * cinA + ci) * HW;
            wsrc = WA + ((size_t)(ocg * 8) * cinA + ci) * 9;
            wstride = cinA * 9;
        } else {
            int cj = ci - cinA;
            src = inB + ((size_t)n * cinB + cj) * HW;
            wsrc = WB + ((size_t)(ocg * 8) * cinB + cj) * 9;
            wstride = cinB * 9;
        }
        // stage padded 30x30 input plane
        for (int idx = tid; idx < 900; idx += 224) {
            int rr = idx / 30 - 1;
            int cc = idx % 30 - 1;
            float v = 0.f;
            if (rr >= 0 && rr < IMG_H && cc >= 0 && cc < IMG_W)
                v = src[rr * IMG_W + cc];
            s_in[idx] = v;
        }
        // stage 8 oc x 9 weights (padded stride 12 for float4 loads)
        if (tid < 72) {
            int oc = tid / 9, k = tid % 9;
            s_w[oc * 12 + k] = wsrc[oc * wstride + k];
        }
        __syncthreads();

        if (active) {
            float vin[6][3];
#pragma unroll
            for (int i = 0; i < 6; ++i)
#pragma unroll
                for (int j = 0; j < 3; ++j)
                    vin[i][j] = s_in[(r0 + i) * 30 + (tc + j)];

#pragma unroll
            for (int oc = 0; oc < 8; ++oc) {
                float4 w0 = *(const float4*)&s_w[oc * 12];
                float4 w1 = *(const float4*)&s_w[oc * 12 + 4];
                float  w8 = s_w[oc * 12 + 8];
#pragma unroll
                for (int p = 0; p < 4; ++p) {
                    float s = acc[oc][p];
                    s = fmaf(w0.x, vin[p    ][0], s);
                    s = fmaf(w0.y, vin[p    ][1], s);
                    s = fmaf(w0.z, vin[p    ][2], s);
                    s = fmaf(w0.w, vin[p + 1][0], s);
                    s = fmaf(w1.x, vin[p + 1][1], s);
                    s = fmaf(w1.y, vin[p + 1][2], s);
                    s = fmaf(w1.z, vin[p + 2][0], s);
                    s = fmaf(w1.w, vin[p + 2][1], s);
                    s = fmaf(w8 , vin[p + 2][2], s);
                    acc[oc][p] = s;
                }
            }
        }
        __syncthreads();
    }

    if (!active) return;
#pragma unroll
    for (int oc = 0; oc < 8; ++oc) {
        int ocGlob = ocg * 8 + oc;
        float b = bias ? bias[ocGlob] : 0.f;
#pragma unroll
        for (int p = 0; p < 4; ++p) {
            int px = (r0 + p) * IMG_W + tc;
            float v = acc[oc][p] + b;
            if (pre) v += pre[(size_t)n * preStride + (size_t)ocGlob * HW + px];
            out[((size_t)n * OC + ocGlob) * HW + px] = v;
        }
    }
}

// ---------------- LSTM pointwise gates ----------------
__device__ __forceinline__ float sigmoidf_(float x) {
    return 1.0f / (1.0f + __expf(-x));
}

__global__ void pointwise_kernel(
    const float* __restrict__ gates,  // (B, 4*HC, 784), gate-major within channel
    const float* __restrict__ Wp,     // (3, 1, HC, 784)  [i, f, o]
    float* __restrict__ h, float* __restrict__ c,
    int HC,
    float* __restrict__ y, int t)     // y: (B, T, HC, 784), may be null
{
    int idx = blockIdx.x * blockDim.x + threadIdx.x;
    int total = BATCH * HC * HW;
    if (idx >= total) return;
    int px = idx % HW;
    int hc = (idx / HW) % HC;
    int b  = idx / (HW * HC);

    const float* g = gates + (size_t)b * 4 * HC * HW;
    float g0 = g[(0 * HC + hc) * HW + px];
    float g1 = g[(1 * HC + hc) * HW + px];
    float g2 = g[(2 * HC + hc) * HW + px];
    float g3 = g[(3 * HC + hc) * HW + px];
    float cv = c[idx];
    float pi = Wp[(0 * HC + hc) * HW + px];
    float pf = Wp[(1 * HC + hc) * HW + px];
    float po = Wp[(2 * HC + hc) * HW + px];

    float gi = sigmoidf_(g0 + cv * pi);
    float gf = sigmoidf_(g1 + cv * pf);
    float cc = gf * cv + gi * tanhf(g2);
    float go = sigmoidf_(g3 + cc * po);
    float hv = go * tanhf(cc);

    c[idx] = cc;
    h[idx] = hv;
    if (y) y[(((size_t)b * TSTEPS + t) * HC + hc) * HW + px] = hv;
}

// ---------------- host launch ----------------
extern "C" void kernel_launch(void* const* d_in, const int* in_sizes, int n_in,
                              void* d_out, int out_size)
{
    const float* x   = (const float*)d_in[0];
    const float* Wx0 = (const float*)d_in[1];
    const float* bx0 = (const float*)d_in[2];
    const float* Wh0 = (const float*)d_in[3];
    const float* Wp0 = (const float*)d_in[4];
    const float* Wx1 = (const float*)d_in[5];
    const float* bx1 = (const float*)d_in[6];
    const float* Wh1 = (const float*)d_in[7];
    const float* Wp1 = (const float*)d_in[8];
    const float* Wx2 = (const float*)d_in[9];
    const float* bx2 = (const float*)d_in[10];
    const float* Wh2 = (const float*)d_in[11];
    const float* Wp2 = (const float*)d_in[12];
    float* y = (float*)d_out;

    float *gx0, *gates, *state;
    cudaGetSymbolAddress((void**)&gx0,   g_gx0);
    cudaGetSymbolAddress((void**)&gates, g_gates);
    cudaGetSymbolAddress((void**)&state, g_state);

    float* h0 = state + OFF_H0;
    float* c0 = state + OFF_C0;
    float* h1 = state + OFF_H1;
    float* c1 = state + OFF_C1;
    float* h2 = state + OFF_H2;
    float* c2 = state + OFF_C2;

    // zero initial states
    init_zero_kernel<<<(NSTATE + 255) / 256, 256>>>(state, NSTATE);

    // batched gx0 = conv(x, Wx0) + bx0 over all B*T frames
    conv3x3_kernel<<<dim3(BATCH * TSTEPS, (4 * HC0) / 8), 224>>>(
        x, CIN0, Wx0, nullptr, 0, nullptr, bx0, nullptr, 0, gx0, 4 * HC0);

    const size_t gx0FrameStride = (size_t)4 * HC0 * HW;       // per t
    const size_t gx0BatchStride = (size_t)TSTEPS * 4 * HC0 * HW; // per b

    for (int t = 0; t < TSTEPS; ++t) {
        // --- layer 0: gates = gx0[b,t] + conv(h0, Wh0)
        conv3x3_kernel<<<dim3(BATCH, (4 * HC0) / 8), 224>>>(
            h0, HC0, Wh0, nullptr, 0, nullptr, nullptr,
            gx0 + (size_t)t * gx0FrameStride, gx0BatchStride,
            gates, 4 * HC0);
        pointwise_kernel<<<(BATCH * HC0 * HW + 255) / 256, 256>>>(
            gates, Wp0, h0, c0, HC0, nullptr, t);

        // --- layer 1: gates = conv(h0, Wx1) + conv(h1, Wh1) + bx1
        conv3x3_kernel<<<dim3(BATCH, (4 * HC1) / 8), 224>>>(
            h0, HC0, Wx1, h1, HC1, Wh1, bx1, nullptr, 0,
            gates, 4 * HC1);
        pointwise_kernel<<<(BATCH * HC1 * HW + 255) / 256, 256>>>(
            gates, Wp1, h1, c1, HC1, nullptr, t);

        // --- layer 2: gates = conv(h1, Wx2) + conv(h2, Wh2) + bx2
        conv3x3_kernel<<<dim3(BATCH, (4 * HC2) / 8), 224>>>(
            h1, HC1, Wx2, h2, HC2, Wh2, bx2, nullptr, 0,
            gates, 4 * HC2);
        pointwise_kernel<<<(BATCH * HC2 * HW + 255) / 256, 256>>>(
            gates, Wp2, h2, c2, HC2, y, t);
    }
}

// round 2
// speedup vs baseline: 3.6823x; 3.6823x over previous
#include <cuda_runtime.h>
#include <cuda_bf16.h>
#include <math.h>
#include <stdint.h>

// ---------------- problem constants ----------------
#define BATCH 8
#define TSTEPS 16
#define CIN0 192
#define HC0 64
#define HC1 32
#define HC2 64
#define IMG_H 28
#define IMG_W 28
#define HW 784

// ---------------- device scratch (no allocs allowed) ----------------
__device__ float g_gx0[(size_t)BATCH * TSTEPS * 4 * HC0 * HW];
__device__ float g_gates[(size_t)BATCH * 4 * 64 * HW];
#define OFF_H0 0
#define OFF_C0 (OFF_H0 + BATCH * HC0 * HW)
#define OFF_H1 (OFF_C0 + BATCH * HC0 * HW)
#define OFF_C1 (OFF_H1 + BATCH * HC1 * HW)
#define OFF_H2 (OFF_C1 + BATCH * HC1 * HW)
#define OFF_C2 (OFF_H2 + BATCH * HC2 * HW)
#define NSTATE (OFF_C2 + BATCH * HC2 * HW)
__device__ float g_state[NSTATE];

__global__ void init_zero_kernel(float* p, int n) {
    int i = blockIdx.x * blockDim.x + threadIdx.x;
    if (i < n) p[i] = 0.f;
}

// ---------------- tf32 helpers ----------------
__device__ __forceinline__ uint32_t f2tf32(float f) {
    uint32_t u;
    asm("cvt.rna.tf32.f32 %0, %1;" : "=r"(u) : "f"(f));
    return u;
}

__device__ __forceinline__ void mma_tf32(float c[4],
                                         uint32_t a0, uint32_t a1, uint32_t a2, uint32_t a3,
                                         uint32_t b0, uint32_t b1) {
    asm volatile(
        "mma.sync.aligned.m16n8k8.row.col.f32.tf32.tf32.f32 "
        "{%0,%1,%2,%3}, {%4,%5,%6,%7}, {%8,%9}, {%0,%1,%2,%3};"
        : "+f"(c[0]), "+f"(c[1]), "+f"(c[2]), "+f"(c[3])
        : "r"(a0), "r"(a1), "r"(a2), "r"(a3), "r"(b0), "r"(b1));
}

// ---------------- conv 3x3 SAME via implicit GEMM (tf32 MMA) ----------------
// Block: one frame n, 64-oc tile (blockIdx.y), 4-row pixel tile (blockIdx.z).
// 8 warps: warp_m = wid&3 (16 oc each), warp_n = wid>>2 (56 px each).
// K loop: chunks of 8 input channels staged in smem; 9 taps = 9 shifted GEMMs.
#define SIN_STR 200  // 6*30=180 rows, padded so (stride mod 32)==8 -> conflict-free B loads

__global__ void __launch_bounds__(256) conv3x3_mma(
    const float* __restrict__ inA, int cinA, const float* __restrict__ WA,
    const float* __restrict__ inB, int cinB, const float* __restrict__ WB,
    const float* __restrict__ bias,
    const float* __restrict__ pre, size_t preStride,
    float* __restrict__ out, int OC)
{
    __shared__ uint32_t s_in[8 * SIN_STR];   // 8 cins x (6 rows x 30 cols) tf32
    __shared__ uint32_t s_w[9 * 64 * 8];     // [tap][oc(64)][ci(8)] tf32

    const int n       = blockIdx.x;
    const int ocbase  = blockIdx.y * 64;
    const int rowbase = blockIdx.z * 4;

    const int tid    = threadIdx.x;
    const int lane   = tid & 31;
    const int wid    = tid >> 5;
    const int warp_m = wid & 3;
    const int warp_n = wid >> 2;
    const int g      = lane >> 2;   // group id
    const int ctg    = lane & 3;    // thread-in-group

    // per-thread pixel offsets (within the padded 6x30 tile) for 7 n8 subtiles
    int off[7];
#pragma unroll
    for (int s = 0; s < 7; ++s) {
        int nl = warp_n * 56 + s * 8 + g;   // 0..111
        int r = nl / 28;
        int c = nl - r * 28;
        off[s] = r * 30 + c;
    }

    float acc[7][4];
#pragma unroll
    for (int s = 0; s < 7; ++s)
#pragma unroll
        for (int j = 0; j < 4; ++j) acc[s][j] = 0.f;

    const int chunks = (cinA + cinB) >> 3;
    for (int ch = 0; ch < chunks; ++ch) {
        const float* src;
        const float* W;
        int CINW, cib;
        int cstart = ch * 8;
        if (cstart < cinA) {
            src = inA + ((size_t)n * cinA + cstart) * HW;
            W = WA; CINW = cinA; cib = cstart;
        } else {
            int c1 = cstart - cinA;
            src = inB + ((size_t)n * cinB + c1) * HW;
            W = WB; CINW = cinB; cib = c1;
        }
        __syncthreads();

        // stage 8 input planes: padded rows [rowbase-1, rowbase+4], cols [-1,28]
        for (int idx = tid; idx < 8 * 180; idx += 256) {
            int ci  = idx / 180;
            int rem = idx - ci * 180;
            int pr  = rem / 30;
            int pc  = rem - pr * 30;
            int gr  = rowbase + pr - 1;
            int gc  = pc - 1;
            float v = 0.f;
            if (gr >= 0 && gr < IMG_H && gc >= 0 && gc < IMG_W)
                v = src[(size_t)ci * HW + gr * IMG_W + gc];
            s_in[ci * SIN_STR + rem] = f2tf32(v);
        }
        // stage weights: s_w[tap][oc][ci]
        for (int idx = tid; idx < 4608; idx += 256) {
            int tap = idx >> 9;
            int r2  = idx & 511;
            int oc  = r2 >> 3;
            int ci  = r2 & 7;
            float w = W[((size_t)(ocbase + oc) * CINW + (cib + ci)) * 9 + tap];
            s_w[idx] = f2tf32(w);
        }
        __syncthreads();

#pragma unroll
        for (int kr = 0; kr < 3; ++kr) {
#pragma unroll
            for (int kc = 0; kc < 3; ++kc) {
                const int tap = kr * 3 + kc;
                const uint32_t* wp = s_w + tap * 512 + (warp_m * 16 + g) * 8 + ctg;
                uint32_t a0 = wp[0];
                uint32_t a1 = wp[64];  // oc+8
                uint32_t a2 = wp[4];   // ci+4
                uint32_t a3 = wp[68];
                const int bbase = ctg * SIN_STR + kr * 30 + kc;
#pragma unroll
                for (int s = 0; s < 7; ++s) {
                    uint32_t b0 = s_in[bbase + off[s]];
                    uint32_t b1 = s_in[bbase + off[s] + 4 * SIN_STR];
                    mma_tf32(acc[s], a0, a1, a2, a3, b0, b1);
                }
            }
        }
    }

    // ---- epilogue ----
    const int ocr0 = ocbase + warp_m * 16 + g;
    const int ocr1 = ocr0 + 8;
    float bv0 = 0.f, bv1 = 0.f;
    if (bias) { bv0 = bias[ocr0]; bv1 = bias[ocr1]; }

#pragma unroll
    for (int s = 0; s < 7; ++s) {
#pragma unroll
        for (int j = 0; j < 2; ++j) {
            int nl = warp_n * 56 + s * 8 + 2 * ctg + j;
            int r = nl / 28;
            int c = nl - r * 28;
            int px = (rowbase + r) * IMG_W + c;
            float v0 = acc[s][j]     + bv0;
            float v1 = acc[s][2 + j] + bv1;
            if (pre) {
                v0 += pre[(size_t)n * preStride + (size_t)ocr0 * HW + px];
                v1 += pre[(size_t)n * preStride + (size_t)ocr1 * HW + px];
            }
            out[((size_t)n * OC + ocr0) * HW + px] = v0;
            out[((size_t)n * OC + ocr1) * HW + px] = v1;
        }
    }
}

// ---------------- LSTM pointwise gates ----------------
__device__ __forceinline__ float sigmoidf_(float x) {
    return 1.0f / (1.0f + __expf(-x));
}

__global__ void pointwise_kernel(
    const float* __restrict__ gates,  // (B, 4*HC, 784)
    const float* __restrict__ Wp,     // (3, 1, HC, 784)  [i, f, o]
    float* __restrict__ h, float* __restrict__ c,
    int HC,
    float* __restrict__ y, int t)     // y: (B, T, HC, 784), may be null
{
    int idx = blockIdx.x * blockDim.x + threadIdx.x;
    int total = BATCH * HC * HW;
    if (idx >= total) return;
    int px = idx % HW;
    int hc = (idx / HW) % HC;
    int b  = idx / (HW * HC);

    const float* gp = gates + (size_t)b * 4 * HC * HW;
    float g0 = gp[(0 * HC + hc) * HW + px];
    float g1 = gp[(1 * HC + hc) * HW + px];
    float g2 = gp[(2 * HC + hc) * HW + px];
    float g3 = gp[(3 * HC + hc) * HW + px];
    float cv = c[idx];
    float pi = Wp[(0 * HC + hc) * HW + px];
    float pf = Wp[(1 * HC + hc) * HW + px];
    float po = Wp[(2 * HC + hc) * HW + px];

    float gi = sigmoidf_(g0 + cv * pi);
    float gf = sigmoidf_(g1 + cv * pf);
    float cc = gf * cv + gi * tanhf(g2);
    float go = sigmoidf_(g3 + cc * po);
    float hv = go * tanhf(cc);

    c[idx] = cc;
    h[idx] = hv;
    if (y) y[(((size_t)b * TSTEPS + t) * HC + hc) * HW + px] = hv;
}

// ---------------- host launch ----------------
extern "C" void kernel_launch(void* const* d_in, const int* in_sizes, int n_in,
                              void* d_out, int out_size)
{
    const float* x   = (const float*)d_in[0];
    const float* Wx0 = (const float*)d_in[1];
    const float* bx0 = (const float*)d_in[2];
    const float* Wh0 = (const float*)d_in[3];
    const float* Wp0 = (const float*)d_in[4];
    const float* Wx1 = (const float*)d_in[5];
    const float* bx1 = (const float*)d_in[6];
    const float* Wh1 = (const float*)d_in[7];
    const float* Wp1 = (const float*)d_in[8];
    const float* Wx2 = (const float*)d_in[9];
    const float* bx2 = (const float*)d_in[10];
    const float* Wh2 = (const float*)d_in[11];
    const float* Wp2 = (const float*)d_in[12];
    float* y = (float*)d_out;

    float *gx0, *gates, *state;
    cudaGetSymbolAddress((void**)&gx0,   g_gx0);
    cudaGetSymbolAddress((void**)&gates, g_gates);
    cudaGetSymbolAddress((void**)&state, g_state);

    float* h0 = state + OFF_H0;
    float* c0 = state + OFF_C0;
    float* h1 = state + OFF_H1;
    float* c1 = state + OFF_C1;
    float* h2 = state + OFF_H2;
    float* c2 = state + OFF_C2;

    init_zero_kernel<<<(NSTATE + 255) / 256, 256>>>(state, NSTATE);

    // batched gx0 = conv(x, Wx0) + bx0 over all B*T frames
    conv3x3_mma<<<dim3(BATCH * TSTEPS, (4 * HC0) / 64, 7), 256>>>(
        x, CIN0, Wx0, nullptr, 0, nullptr, bx0, nullptr, 0, gx0, 4 * HC0);

    const size_t gx0FrameStride = (size_t)4 * HC0 * HW;           // per t
    const size_t gx0BatchStride = (size_t)TSTEPS * 4 * HC0 * HW;  // per b

    for (int t = 0; t < TSTEPS; ++t) {
        // --- layer 0: gates = gx0[b,t] + conv(h0, Wh0)
        conv3x3_mma<<<dim3(BATCH, (4 * HC0) / 64, 7), 256>>>(
            h0, HC0, Wh0, nullptr, 0, nullptr, nullptr,
            gx0 + (size_t)t * gx0FrameStride, gx0BatchStride,
            gates, 4 * HC0);
        pointwise_kernel<<<(BATCH * HC0 * HW + 255) / 256, 256>>>(
            gates, Wp0, h0, c0, HC0, nullptr, t);

        // --- layer 1: gates = conv(h0, Wx1) + conv(h1, Wh1) + bx1
        conv3x3_mma<<<dim3(BATCH, (4 * HC1) / 64, 7), 256>>>(
            h0, HC0, Wx1, h1, HC1, Wh1, bx1, nullptr, 0,
            gates, 4 * HC1);
        pointwise_kernel<<<(BATCH * HC1 * HW + 255) / 256, 256>>>(
            gates, Wp1, h1, c1, HC1, nullptr, t);

        // --- layer 2: gates = conv(h1, Wx2) + conv(h2, Wh2) + bx2
        conv3x3_mma<<<dim3(BATCH, (4 * HC2) / 64, 7), 256>>>(
            h1, HC1, Wx2, h2, HC2, Wh2, bx2, nullptr, 0,
            gates, 4 * HC2);
        pointwise_kernel<<<(BATCH * HC2 * HW + 255) / 256, 256>>>(
            gates, Wp2, h2, c2, HC2, y, t);
    }
}

// round 4
// speedup vs baseline: 4.3110x; 1.1708x over previous
#include <cuda_runtime.h>
#include <cuda_bf16.h>
#include <math.h>
#include <stdint.h>

// ---------------- problem constants ----------------
#define BATCH 8
#define TSTEPS 16
#define CIN0 192
#define HC0 64
#define HC1 32
#define HC2 64
#define IMG_H 28
#define IMG_W 28
#define HW 784

// ---------------- device scratch (no allocs allowed) ----------------
__device__ float g_gx0[(size_t)BATCH * TSTEPS * 4 * HC0 * HW];
// double-buffered h (a/b) + single c per layer
#define SZ0 (BATCH * HC0 * HW)
#define SZ1 (BATCH * HC1 * HW)
#define SZ2 (BATCH * HC2 * HW)
#define OFF_H0A 0
#define OFF_H0B (OFF_H0A + SZ0)
#define OFF_C0  (OFF_H0B + SZ0)
#define OFF_H1A (OFF_C0  + SZ0)
#define OFF_H1B (OFF_H1A + SZ1)
#define OFF_C1  (OFF_H1B + SZ1)
#define OFF_H2A (OFF_C1  + SZ1)
#define OFF_H2B (OFF_H2A + SZ2)
#define OFF_C2  (OFF_H2B + SZ2)
#define NSTATE  (OFF_C2  + SZ2)
__device__ float g_state[NSTATE];

__global__ void init_zero_kernel(float* p, int n) {
    int i = blockIdx.x * blockDim.x + threadIdx.x;
    if (i < n) p[i] = 0.f;
}

// ---------------- tf32 helpers ----------------
__device__ __forceinline__ uint32_t f2tf32(float f) {
    uint32_t u;
    asm("cvt.rna.tf32.f32 %0, %1;" : "=r"(u) : "f"(f));
    return u;
}

__device__ __forceinline__ void mma_tf32(float c[4],
                                         uint32_t a0, uint32_t a1, uint32_t a2, uint32_t a3,
                                         uint32_t b0, uint32_t b1) {
    asm volatile(
        "mma.sync.aligned.m16n8k8.row.col.f32.tf32.tf32.f32 "
        "{%0,%1,%2,%3}, {%4,%5,%6,%7}, {%8,%9}, {%0,%1,%2,%3};"
        : "+f"(c[0]), "+f"(c[1]), "+f"(c[2]), "+f"(c[3])
        : "r"(a0), "r"(a1), "r"(a2), "r"(a3), "r"(b0), "r"(b1));
}

__device__ __forceinline__ float sigmoidf_(float x) {
    return 1.0f / (1.0f + __expf(-x));
}

// ---------------- fused conv 3x3 (tf32 MMA) + optional LSTM pointwise ----------
// M-row mapping: m (0..63) -> oc = (m>>4)*HC + blockIdx.y*16 + (m&15)
// warp_m == gate; 16 hidden-channel slice per block -> pointwise fusable.
// Grid: (frames, HC/16, 7 row-tiles of 4 rows). 256 threads, 8 warps (4M x 2N).
// hin (conv input h) is READ-ONLY; hout is a DIFFERENT buffer -> no cross-block race.
#define SIN_STR 200   // padded stride: (200 mod 32)==8 -> conflict-free B LDS

struct SmemU {
    union {
        struct {
            uint32_t in[8 * SIN_STR];   // 8 cins x (6 rows x 30 cols)
            uint32_t w[9 * 64 * 8];     // [tap][m(64)][ci(8)]
        } mm;
        float gates[4 * 16 * 112];      // [gate][hcl][nl]
    };
};

__global__ void __launch_bounds__(256) conv3x3_cell(
    const float* __restrict__ inA, int cinA, const float* __restrict__ WA,
    const float* __restrict__ inB, int cinB, const float* __restrict__ WB,
    const float* __restrict__ bias,
    const float* __restrict__ pre, size_t preStride,
    int HC,
    // plain output path (hout == nullptr):
    float* __restrict__ out,
    // fused LSTM path:
    const float* __restrict__ Wp,
    float* __restrict__ hout, float* __restrict__ c,
    float* __restrict__ yout, int t)
{
    __shared__ SmemU sm;

    const int n       = blockIdx.x;
    const int hcb     = blockIdx.y * 16;   // 16-channel slice base
    const int rowbase = blockIdx.z * 4;

    const int tid    = threadIdx.x;
    const int lane   = tid & 31;
    const int wid    = tid >> 5;
    const int warp_m = wid & 3;            // == gate for fused path
    const int warp_n = wid >> 2;
    const int g      = lane >> 2;
    const int ctg    = lane & 3;

    int off[7];
#pragma unroll
    for (int s = 0; s < 7; ++s) {
        int nl = warp_n * 56 + s * 8 + g;
        int r = nl / 28;
        off[s] = r * 30 + (nl - r * 28);
    }

    float acc[7][4];
#pragma unroll
    for (int s = 0; s < 7; ++s)
#pragma unroll
        for (int j = 0; j < 4; ++j) acc[s][j] = 0.f;

    const int chunks = (cinA + cinB) >> 3;

    float rin[6];
    float rw[18];

    // ---- prefetch loader: chunk ch -> registers ----
    auto load_chunk = [&](int ch) {
        const int cstart = ch * 8;
        const float* src;
        const float* W;
        int CINW, cib;
        if (cstart < cinA) {
            src = inA + ((size_t)n * cinA + cstart) * HW;
            W = WA; CINW = cinA; cib = cstart;
        } else {
            int c1 = cstart - cinA;
            src = inB + ((size_t)n * cinB + c1) * HW;
            W = WB; CINW = cinB; cib = c1;
        }
#pragma unroll
        for (int k = 0; k < 6; ++k) {
            int idx = tid + k * 256;
            float v = 0.f;
            if (idx < 1440) {
                int ci  = idx / 180;
                int rem = idx - ci * 180;
                int pr  = rem / 30;
                int gr  = rowbase + pr - 1;
                int gc  = (rem - pr * 30) - 1;
                if (gr >= 0 && gr < IMG_H && gc >= 0 && gc < IMG_W)
                    v = src[(size_t)ci * HW + gr * IMG_W + gc];
            }
            rin[k] = v;
        }
#pragma unroll
        for (int k = 0; k < 18; ++k) {
            int idx = tid + k * 256;       // < 4608 always
            int tap = idx >> 9;
            int r2  = idx & 511;
            int m   = r2 >> 3;
            int ci  = r2 & 7;
            int oc  = (m >> 4) * HC + hcb + (m & 15);
            rw[k] = W[((size_t)oc * CINW + (cib + ci)) * 9 + tap];
        }
    };

    load_chunk(0);

    for (int ch = 0; ch < chunks; ++ch) {
        __syncthreads();   // previous MMA phase done reading smem
#pragma unroll
        for (int k = 0; k < 6; ++k) {
            int idx = tid + k * 256;
            if (idx < 1440) {
                int ci  = idx / 180;
                int rem = idx - ci * 180;
                sm.mm.in[ci * SIN_STR + rem] = f2tf32(rin[k]);
            }
        }
#pragma unroll
        for (int k = 0; k < 18; ++k) {
            int idx = tid + k * 256;
            sm.mm.w[idx] = f2tf32(rw[k]);
        }
        __syncthreads();

        if (ch + 1 < chunks) load_chunk(ch + 1);   // LDGs overlap MMA phase

#pragma unroll
        for (int kr = 0; kr < 3; ++kr) {
#pragma unroll
            for (int kc = 0; kc < 3; ++kc) {
                const int tap = kr * 3 + kc;
                const uint32_t* wp = sm.mm.w + tap * 512 + (warp_m * 16 + g) * 8 + ctg;
                uint32_t a0 = wp[0];
                uint32_t a1 = wp[64];
                uint32_t a2 = wp[4];
                uint32_t a3 = wp[68];
                const int bbase = ctg * SIN_STR + kr * 30 + kc;
#pragma unroll
                for (int s = 0; s < 7; ++s) {
                    uint32_t b0 = sm.mm.in[bbase + off[s]];
                    uint32_t b1 = sm.mm.in[bbase + off[s] + 4 * SIN_STR];
                    mma_tf32(acc[s], a0, a1, a2, a3, b0, b1);
                }
            }
        }
    }

    // ---- epilogue ----
    const int oc0 = warp_m * HC + hcb + g;
    const int oc1 = oc0 + 8;
    float bv0 = 0.f, bv1 = 0.f;
    if (bias) { bv0 = bias[oc0]; bv1 = bias[oc1]; }

    if (hout == nullptr) {
        // plain conv output (gx0 precompute)
#pragma unroll
        for (int s = 0; s < 7; ++s) {
#pragma unroll
            for (int j = 0; j < 2; ++j) {
                int nl = warp_n * 56 + s * 8 + 2 * ctg + j;
                int r = nl / 28;
                int px = (rowbase + r) * IMG_W + (nl - r * 28);
                float v0 = acc[s][j]     + bv0;
                float v1 = acc[s][2 + j] + bv1;
                if (pre) {
                    v0 += pre[(size_t)n * preStride + (size_t)oc0 * HW + px];
                    v1 += pre[(size_t)n * preStride + (size_t)oc1 * HW + px];
                }
                out[((size_t)n * 4 * HC + oc0) * HW + px] = v0;
                out[((size_t)n * 4 * HC + oc1) * HW + px] = v1;
            }
        }
        return;
    }

    // fused LSTM: exchange gates through smem, then pointwise
    __syncthreads();   // all MMA reads of sm.mm finished before overwrite
#pragma unroll
    for (int s = 0; s < 7; ++s) {
#pragma unroll
        for (int j = 0; j < 2; ++j) {
            int nl = warp_n * 56 + s * 8 + 2 * ctg + j;
            float v0 = acc[s][j]     + bv0;
            float v1 = acc[s][2 + j] + bv1;
            if (pre) {
                int r = nl / 28;
                int px = (rowbase + r) * IMG_W + (nl - r * 28);
                v0 += pre[(size_t)n * preStride + (size_t)oc0 * HW + px];
                v1 += pre[(size_t)n * preStride + (size_t)oc1 * HW + px];
            }
            sm.gates[(warp_m * 16 + g)     * 112 + nl] = v0;
            sm.gates[(warp_m * 16 + g + 8) * 112 + nl] = v1;
        }
    }
    __syncthreads();

    // pointwise over 16 hc x 112 px  (1792 elems, 7 per thread)
#pragma unroll
    for (int k = 0; k < 7; ++k) {
        int e   = tid + k * 256;
        int hcl = e / 112;
        int nl  = e - hcl * 112;
        int r   = nl / 28;
        int px  = (rowbase + r) * IMG_W + (nl - r * 28);
        int hc  = hcb + hcl;

        float g0 = sm.gates[(0 * 16 + hcl) * 112 + nl];
        float g1 = sm.gates[(1 * 16 + hcl) * 112 + nl];
        float g2 = sm.gates[(2 * 16 + hcl) * 112 + nl];
        float g3 = sm.gates[(3 * 16 + hcl) * 112 + nl];

        size_t sidx = ((size_t)n * HC + hc) * HW + px;
        float cv = c[sidx];
        float pi = Wp[(size_t)(0 * HC + hc) * HW + px];
        float pf = Wp[(size_t)(1 * HC + hc) * HW + px];
        float po = Wp[(size_t)(2 * HC + hc) * HW + px];

        float gi = sigmoidf_(g0 + cv * pi);
        float gf = sigmoidf_(g1 + cv * pf);
        float cc = gf * cv + gi * tanhf(g2);
        float go = sigmoidf_(g3 + cc * po);
        float hv = go * tanhf(cc);

        c[sidx] = cc;
        hout[sidx] = hv;
        if (yout)
            yout[(((size_t)n * TSTEPS + t) * HC + hc) * HW + px] = hv;
    }
}

// ---------------- host launch ----------------
extern "C" void kernel_launch(void* const* d_in, const int* in_sizes, int n_in,
                              void* d_out, int out_size)
{
    const float* x   = (const float*)d_in[0];
    const float* Wx0 = (const float*)d_in[1];
    const float* bx0 = (const float*)d_in[2];
    const float* Wh0 = (const float*)d_in[3];
    const float* Wp0 = (const float*)d_in[4];
    const float* Wx1 = (const float*)d_in[5];
    const float* bx1 = (const float*)d_in[6];
    const float* Wh1 = (const float*)d_in[7];
    const float* Wp1 = (const float*)d_in[8];
    const float* Wx2 = (const float*)d_in[9];
    const float* bx2 = (const float*)d_in[10];
    const float* Wh2 = (const float*)d_in[11];
    const float* Wp2 = (const float*)d_in[12];
    float* y = (float*)d_out;

    float *gx0, *state;
    cudaGetSymbolAddress((void**)&gx0,   g_gx0);
    cudaGetSymbolAddress((void**)&state, g_state);

    float* h0buf[2] = { state + OFF_H0A, state + OFF_H0B };
    float* h1buf[2] = { state + OFF_H1A, state + OFF_H1B };
    float* h2buf[2] = { state + OFF_H2A, state + OFF_H2B };
    float* c0 = state + OFF_C0;
    float* c1 = state + OFF_C1;
    float* c2 = state + OFF_C2;

    init_zero_kernel<<<(NSTATE + 255) / 256, 256>>>(state, NSTATE);

    // batched gx0 = conv(x, Wx0) + bx0 over all B*T frames (plain path)
    conv3x3_cell<<<dim3(BATCH * TSTEPS, HC0 / 16, 7), 256>>>(
        x, CIN0, Wx0, nullptr, 0, nullptr, bx0, nullptr, 0,
        HC0, gx0, nullptr, nullptr, nullptr, nullptr, 0);

    const size_t gx0FrameStride = (size_t)4 * HC0 * HW;           // per t
    const size_t gx0BatchStride = (size_t)TSTEPS * 4 * HC0 * HW;  // per b

    for (int t = 0; t < TSTEPS; ++t) {
        const int rb = t & 1;        // read buffer index
        const int wb = rb ^ 1;       // write buffer index
        float* h0r = h0buf[rb]; float* h0w = h0buf[wb];
        float* h1r = h1buf[rb]; float* h1w = h1buf[wb];
        float* h2r = h2buf[rb]; float* h2w = h2buf[wb];

        // layer 0: gates = gx0[b,t] + conv(h0_old, Wh0); writes h0_new, c0
        conv3x3_cell<<<dim3(BATCH, HC0 / 16, 7), 256>>>(
            h0r, HC0, Wh0, nullptr, 0, nullptr, nullptr,
            gx0 + (size_t)t * gx0FrameStride, gx0BatchStride,
            HC0, nullptr, Wp0, h0w, c0, nullptr, t);

        // layer 1: gates = conv(h0_new, Wx1) + conv(h1_old, Wh1) + bx1
        conv3x3_cell<<<dim3(BATCH, HC1 / 16, 7), 256>>>(
            h0w, HC0, Wx1, h1r, HC1, Wh1, bx1, nullptr, 0,
            HC1, nullptr, Wp1, h1w, c1, nullptr, t);

        // layer 2: gates = conv(h1_new, Wx2) + conv(h2_old, Wh2) + bx2; emits y
        conv3x3_cell<<<dim3(BATCH, HC2 / 16, 7), 256>>>(
            h1w, HC1, Wx2, h2r, HC2, Wh2, bx2, nullptr, 0,
            HC2, nullptr, Wp2, h2w, c2, y, t);
    }
}

// round 5
// speedup vs baseline: 6.0396x; 1.4010x over previous
#include <cuda_runtime.h>
#include <cuda_bf16.h>
#include <math.h>
#include <stdint.h>

// ---------------- problem constants ----------------
#define BATCH 8
#define TSTEPS 16
#define CIN0 192
#define HC0 64
#define HC1 32
#define HC2 64
#define IMG_H 28
#define IMG_W 28
#define HW 784

// ---------------- device scratch (no allocs allowed) ----------------
__device__ float g_gx0[(size_t)BATCH * TSTEPS * 4 * HC0 * HW];

// double-buffered h (a/b) + single c per layer
#define SZ0 (BATCH * HC0 * HW)
#define SZ1 (BATCH * HC1 * HW)
#define SZ2 (BATCH * HC2 * HW)
#define OFF_H0A 0
#define OFF_H0B (OFF_H0A + SZ0)
#define OFF_C0  (OFF_H0B + SZ0)
#define OFF_H1A (OFF_C0  + SZ0)
#define OFF_H1B (OFF_H1A + SZ1)
#define OFF_C1  (OFF_H1B + SZ1)
#define OFF_H2A (OFF_C1  + SZ1)
#define OFF_H2B (OFF_H2A + SZ2)
#define OFF_C2  (OFF_H2B + SZ2)
#define NSTATE  (OFF_C2  + SZ2)
__device__ float g_state[NSTATE];

// pre-transposed tf32 weight buffers, layout [y][chunk][tap][m(32)][ci(8)]
// oc(m) = (m>>3)*HC + y*8 + (m&7)
#define WPC 2304                       // words per chunk (9*32*8)
#define WOFF_GX0 0
#define WSZ_GX0 (8 * 24 * WPC)         // y=8, chunks=24
#define WOFF_L0 (WOFF_GX0 + WSZ_GX0)
#define WSZ_L0  (8 * 8 * WPC)          // y=8, chunks=8
#define WOFF_L1 (WOFF_L0 + WSZ_L0)
#define WSZ_L1  (4 * 12 * WPC)         // y=4, chunks=12
#define WOFF_L2 (WOFF_L1 + WSZ_L1)
#define WSZ_L2  (8 * 12 * WPC)         // y=8, chunks=12
#define WTOTAL  (WOFF_L2 + WSZ_L2)
__device__ uint32_t g_wt[WTOTAL];

__global__ void init_zero_kernel(float* p, int n) {
    int i = blockIdx.x * blockDim.x + threadIdx.x;
    if (i < n) p[i] = 0.f;
}

// ---------------- tf32 helpers ----------------
__device__ __forceinline__ uint32_t f2tf32(float f) {
    uint32_t u;
    asm("cvt.rna.tf32.f32 %0, %1;" : "=r"(u) : "f"(f));
    return u;
}

__device__ __forceinline__ void mma_tf32(float c[4],
                                         uint32_t a0, uint32_t a1, uint32_t a2, uint32_t a3,
                                         uint32_t b0, uint32_t b1) {
    asm volatile(
        "mma.sync.aligned.m16n8k8.row.col.f32.tf32.tf32.f32 "
        "{%0,%1,%2,%3}, {%4,%5,%6,%7}, {%8,%9}, {%0,%1,%2,%3};"
        : "+f"(c[0]), "+f"(c[1]), "+f"(c[2]), "+f"(c[3])
        : "r"(a0), "r"(a1), "r"(a2), "r"(a3), "r"(b0), "r"(b1));
}

__device__ __forceinline__ float sigmoidf_(float x) {
    return 1.0f / (1.0f + __expf(-x));
}

// ---------------- weight prep: transpose + tf32 ----------------
// dst layout: [y][ch][tap][m][ci]; oc = (m>>3)*HC + y*8 + (m&7); cin = ch*8+ci
__global__ void prep_weights(const float* __restrict__ WA, int cinA,
                             const float* __restrict__ WB, int cinB,
                             int HC, int chunks, uint32_t* __restrict__ dst, int total)
{
    int idx = blockIdx.x * blockDim.x + threadIdx.x;
    if (idx >= total) return;
    int ci  = idx & 7;
    int m   = (idx >> 3) & 31;
    int tap = (idx >> 8) % 9;
    int chy = idx / WPC;
    int ch  = chy % chunks;
    int y   = chy / chunks;
    int oc  = (m >> 3) * HC + y * 8 + (m & 7);
    int cg  = ch * 8 + ci;
    float w;
    if (cg < cinA) w = WA[((size_t)oc * cinA + cg) * 9 + tap];
    else           w = WB[((size_t)oc * cinB + (cg - cinA)) * 9 + tap];
    dst[idx] = f2tf32(w);
}

// ---------------- fused conv 3x3 (tf32 MMA) + optional LSTM pointwise ----------
// M=32 rows: m -> oc = (m>>3)*HC + blockIdx.y*8 + (m&7)  (4 gates x 8-hc slice)
// Grid: (frames, HC/8, 7 row-tiles of 4 rows). 128 threads = 4 warps (2M x 2N).
// Ping-pong smem pipeline, pre-transposed weights.
#define SIN_STR 200   // (200 mod 32)==8 -> conflict-free B LDS

struct SmemU {
    union {
        struct {
            uint32_t in[2][8 * SIN_STR];  // per stage: 8 cins x (6 rows x 30 cols)
            uint32_t w[2][WPC];           // per stage: [tap][m(32)][ci(8)]
        } mm;
        float gates[4 * 8 * 112];         // [gate][hcl][nl]
    };
};

__global__ void __launch_bounds__(128, 4) conv3x3_cell(
    const float* __restrict__ inA, int cinA,
    const float* __restrict__ inB, int cinB,
    const uint32_t* __restrict__ wt,      // pre-transposed weights for this conv
    const float* __restrict__ bias,
    const float* __restrict__ pre, size_t preStride,
    int HC,
    float* __restrict__ out,              // plain path (hout == nullptr)
    const float* __restrict__ Wp,
    float* __restrict__ hout, float* __restrict__ c,
    float* __restrict__ yout, int t)
{
    __shared__ SmemU sm;

    const int n       = blockIdx.x;
    const int hcb     = blockIdx.y * 8;
    const int rowbase = blockIdx.z * 4;

    const int tid    = threadIdx.x;
    const int lane   = tid & 31;
    const int wid    = tid >> 5;
    const int warp_m = wid & 1;
    const int warp_n = wid >> 1;
    const int g      = lane >> 2;
    const int ctg    = lane & 3;

    const int chunks = (cinA + cinB) >> 3;

    int off[7];
#pragma unroll
    for (int s = 0; s < 7; ++s) {
        int nl = warp_n * 56 + s * 8 + g;
        int r = nl / 28;
        off[s] = r * 30 + (nl - r * 28);
    }

    float acc[7][4];
#pragma unroll
    for (int s = 0; s < 7; ++s)
#pragma unroll
        for (int j = 0; j < 4; ++j) acc[s][j] = 0.f;

    float rin[12];
    uint4 rw4[5];

    auto load_chunk = [&](int ch) {
        const int cstart = ch * 8;
        const float* src = (cstart < cinA)
            ? inA + ((size_t)n * cinA + cstart) * HW
            : inB + ((size_t)n * cinB + (cstart - cinA)) * HW;
#pragma unroll
        for (int k = 0; k < 12; ++k) {
            int idx = tid + k * 128;
            float v = 0.f;
            if (idx < 1440) {
                int ci  = idx / 180;
                int rem = idx - ci * 180;
                int pr  = rem / 30;
                int gr  = rowbase + pr - 1;
                int gc  = (rem - pr * 30) - 1;
                if (gr >= 0 && gr < IMG_H && gc >= 0 && gc < IMG_W)
                    v = src[(size_t)ci * HW + gr * IMG_W + gc];
            }
            rin[k] = v;
        }
        const uint4* wsrc = (const uint4*)(wt + ((size_t)blockIdx.y * chunks + ch) * WPC);
#pragma unroll
        for (int k = 0; k < 5; ++k) {
            int i4 = tid + k * 128;
            if (i4 < 576) rw4[k] = wsrc[i4];
        }
    };

    load_chunk(0);

    for (int ch = 0; ch < chunks; ++ch) {
        const int st = ch & 1;
        // store staged regs into stage st
#pragma unroll
        for (int k = 0; k < 12; ++k) {
            int idx = tid + k * 128;
            if (idx < 1440) {
                int ci  = idx / 180;
                int rem = idx - ci * 180;
                sm.mm.in[st][ci * SIN_STR + rem] = f2tf32(rin[k]);
            }
        }
#pragma unroll
        for (int k = 0; k < 5; ++k) {
            int i4 = tid + k * 128;
            if (i4 < 576) ((uint4*)sm.mm.w[st])[i4] = rw4[k];
        }
        __syncthreads();

        if (ch + 1 < chunks) load_chunk(ch + 1);  // LDGs overlap MMA phase

        const uint32_t* win = sm.mm.in[st];
        const uint32_t* ww  = sm.mm.w[st];
#pragma unroll
        for (int kr = 0; kr < 3; ++kr) {
#pragma unroll
            for (int kc = 0; kc < 3; ++kc) {
                const int tap = kr * 3 + kc;
                const uint32_t* wp = ww + tap * 256 + (warp_m * 16 + g) * 8 + ctg;
                uint32_t a0 = wp[0];
                uint32_t a1 = wp[64];   // m+8
                uint32_t a2 = wp[4];    // ci+4
                uint32_t a3 = wp[68];
                const int bbase = ctg * SIN_STR + kr * 30 + kc;
#pragma unroll
                for (int s = 0; s < 7; ++s) {
                    uint32_t b0 = win[bbase + off[s]];
                    uint32_t b1 = win[bbase + off[s] + 4 * SIN_STR];
                    mma_tf32(acc[s], a0, a1, a2, a3, b0, b1);
                }
            }
        }
    }

    // ---- epilogue ----
    const int m0  = warp_m * 16 + g;          // 0..15
    const int oc0 = (m0 >> 3) * HC + hcb + (m0 & 7);
    const int m1  = m0 + 8;
    const int oc1 = (m1 >> 3) * HC + hcb + (m1 & 7);
    float bv0 = 0.f, bv1 = 0.f;
    if (bias) { bv0 = bias[oc0]; bv1 = bias[oc1]; }

    if (hout == nullptr) {
#pragma unroll
        for (int s = 0; s < 7; ++s) {
#pragma unroll
            for (int j = 0; j < 2; ++j) {
                int nl = warp_n * 56 + s * 8 + 2 * ctg + j;
                int r = nl / 28;
                int px = (rowbase + r) * IMG_W + (nl - r * 28);
                float v0 = acc[s][j]     + bv0;
                float v1 = acc[s][2 + j] + bv1;
                if (pre) {
                    v0 += pre[(size_t)n * preStride + (size_t)oc0 * HW + px];
                    v1 += pre[(size_t)n * preStride + (size_t)oc1 * HW + px];
                }
                out[((size_t)n * 4 * HC + oc0) * HW + px] = v0;
                out[((size_t)n * 4 * HC + oc1) * HW + px] = v1;
            }
        }
        return;
    }

    // fused LSTM: gates through smem, then pointwise
    __syncthreads();   // all MMA reads done before union overwrite
#pragma unroll
    for (int s = 0; s < 7; ++s) {
#pragma unroll
        for (int j = 0; j < 2; ++j) {
            int nl = warp_n * 56 + s * 8 + 2 * ctg + j;
            float v0 = acc[s][j]     + bv0;
            float v1 = acc[s][2 + j] + bv1;
            if (pre) {
                int r = nl / 28;
                int px = (rowbase + r) * IMG_W + (nl - r * 28);
                v0 += pre[(size_t)n * preStride + (size_t)oc0 * HW + px];
                v1 += pre[(size_t)n * preStride + (size_t)oc1 * HW + px];
            }
            sm.gates[((m0 >> 3) * 8 + (m0 & 7)) * 112 + nl] = v0;
            sm.gates[((m1 >> 3) * 8 + (m1 & 7)) * 112 + nl] = v1;
        }
    }
    __syncthreads();

    // pointwise over 8 hc x 112 px  (896 elems, 7 per thread)
#pragma unroll
    for (int k = 0; k < 7; ++k) {
        int e   = tid + k * 128;
        int hcl = e / 112;
        int nl  = e - hcl * 112;
        int r   = nl / 28;
        int px  = (rowbase + r) * IMG_W + (nl - r * 28);
        int hc  = hcb + hcl;

        float g0 = sm.gates[(0 * 8 + hcl) * 112 + nl];
        float g1 = sm.gates[(1 * 8 + hcl) * 112 + nl];
        float g2 = sm.gates[(2 * 8 + hcl) * 112 + nl];
        float g3 = sm.gates[(3 * 8 + hcl) * 112 + nl];

        size_t sidx = ((size_t)n * HC + hc) * HW + px;
        float cv = c[sidx];
        float pi = Wp[(size_t)(0 * HC + hc) * HW + px];
        float pf = Wp[(size_t)(1 * HC + hc) * HW + px];
        float po = Wp[(size_t)(2 * HC + hc) * HW + px];

        float gi = sigmoidf_(g0 + cv * pi);
        float gf = sigmoidf_(g1 + cv * pf);
        float cc = gf * cv + gi * tanhf(g2);
        float go = sigmoidf_(g3 + cc * po);
        float hv = go * tanhf(cc);

        c[sidx] = cc;
        hout[sidx] = hv;
        if (yout)
            yout[(((size_t)n * TSTEPS + t) * HC + hc) * HW + px] = hv;
    }
}

// ---------------- host launch ----------------
extern "C" void kernel_launch(void* const* d_in, const int* in_sizes, int n_in,
                              void* d_out, int out_size)
{
    const float* x   = (const float*)d_in[0];
    const float* Wx0 = (const float*)d_in[1];
    const float* bx0 = (const float*)d_in[2];
    const float* Wh0 = (const float*)d_in[3];
    const float* Wp0 = (const float*)d_in[4];
    const float* Wx1 = (const float*)d_in[5];
    const float* bx1 = (const float*)d_in[6];
    const float* Wh1 = (const float*)d_in[7];
    const float* Wp1 = (const float*)d_in[8];
    const float* Wx2 = (const float*)d_in[9];
    const float* bx2 = (const float*)d_in[10];
    const float* Wh2 = (const float*)d_in[11];
    const float* Wp2 = (const float*)d_in[12];
    float* y = (float*)d_out;

    float *gx0, *state;
    uint32_t* wt;
    cudaGetSymbolAddress((void**)&gx0,   g_gx0);
    cudaGetSymbolAddress((void**)&state, g_state);
    cudaGetSymbolAddress((void**)&wt,    g_wt);

    float* h0buf[2] = { state + OFF_H0A, state + OFF_H0B };
    float* h1buf[2] = { state + OFF_H1A, state + OFF_H1B };
    float* h2buf[2] = { state + OFF_H2A, state + OFF_H2B };
    float* c0 = state + OFF_C0;
    float* c1 = state + OFF_C1;
    float* c2 = state + OFF_C2;

    init_zero_kernel<<<(NSTATE + 255) / 256, 256>>>(state, NSTATE);

    // ---- prep transposed tf32 weights ----
    prep_weights<<<(WSZ_GX0 + 255) / 256, 256>>>(Wx0, CIN0, nullptr, 0, HC0, 24, wt + WOFF_GX0, WSZ_GX0);
    prep_weights<<<(WSZ_L0  + 255) / 256, 256>>>(Wh0, HC0,  nullptr, 0, HC0,  8, wt + WOFF_L0,  WSZ_L0);
    prep_weights<<<(WSZ_L1  + 255) / 256, 256>>>(Wx1, HC0,  Wh1, HC1, HC1, 12, wt + WOFF_L1,  WSZ_L1);
    prep_weights<<<(WSZ_L2  + 255) / 256, 256>>>(Wx2, HC1,  Wh2, HC2, HC2, 12, wt + WOFF_L2,  WSZ_L2);

    // batched gx0 = conv(x, Wx0) + bx0 over all B*T frames (plain path)
    conv3x3_cell<<<dim3(BATCH * TSTEPS, HC0 / 8, 7), 128>>>(
        x, CIN0, nullptr, 0, wt + WOFF_GX0, bx0, nullptr, 0,
        HC0, gx0, nullptr, nullptr, nullptr, nullptr, 0);

    const size_t gx0FrameStride = (size_t)4 * HC0 * HW;           // per t
    const size_t gx0BatchStride = (size_t)TSTEPS * 4 * HC0 * HW;  // per b

    for (int t = 0; t < TSTEPS; ++t) {
        const int rb = t & 1;
        const int wb = rb ^ 1;
        float* h0r = h0buf[rb]; float* h0w = h0buf[wb];
        float* h1r = h1buf[rb]; float* h1w = h1buf[wb];
        float* h2r = h2buf[rb]; float* h2w = h2buf[wb];

        // layer 0: gates = gx0[b,t] + conv(h0_old, Wh0)
        conv3x3_cell<<<dim3(BATCH, HC0 / 8, 7), 128>>>(
            h0r, HC0, nullptr, 0, wt + WOFF_L0, nullptr,
            gx0 + (size_t)t * gx0FrameStride, gx0BatchStride,
            HC0, nullptr, Wp0, h0w, c0, nullptr, t);

        // layer 1: gates = conv(h0_new, Wx1) + conv(h1_old, Wh1) + bx1
        conv3x3_cell<<<dim3(BATCH, HC1 / 8, 7), 128>>>(
            h0w, HC0, h1r, HC1, wt + WOFF_L1, bx1, nullptr, 0,
            HC1, nullptr, Wp1, h1w, c1, nullptr, t);

        // layer 2: gates = conv(h1_new, Wx2) + conv(h2_old, Wh2) + bx2; emits y
        conv3x3_cell<<<dim3(BATCH, HC2 / 8, 7), 128>>>(
            h1w, HC1, h2r, HC2, wt + WOFF_L2, bx2, nullptr, 0,
            HC2, nullptr, Wp2, h2w, c2, y, t);
    }
}